// round 6
// baseline (speedup 1.0000x reference)
#include <cuda_runtime.h>
#include <cuda_bf16.h>

// Problem constants
#define BB 8
#define C1 128
#define C2 256
#define NN 1024
#define HEADS 8
#define DD 32
#define KC 3
#define SCALE 0.17677669529663687f   // 32^-0.5
#define LOG2E 1.4426950408889634f
#define QSC (SCALE * LOG2E)

// Scratch (device globals; no allocation allowed)
__device__ float g_xf[BB * C2 * NN];                      // proj_in out / identity
__device__ float g_prob[BB * KC * NN];                    // cluster probs [b][k][n]
__device__ float g_att[BB * C2 * NN];                     // attention out [b][c][n]
// prescaled qkv: [part(q,k,v)][cluster][b][c][n] bf16
__device__ __nv_bfloat16 g_pre[3 * KC * BB * C2 * NN];

// ---------------------------------------------------------------------------
__device__ __forceinline__ float ex2(float x) {
    float r; asm("ex2.approx.f32 %0, %1;" : "=f"(r) : "f"(x)); return r;
}
__device__ __forceinline__ unsigned pack_bf2(float lo, float hi) {
    unsigned r;
    asm("cvt.rn.bf16x2.f32 %0, %1, %2;" : "=r"(r) : "f"(hi), "f"(lo));
    return r;
}
__device__ __forceinline__ unsigned saddr(const void* p) {
    return (unsigned)__cvta_generic_to_shared(p);
}
__device__ __forceinline__ void ldsm4(unsigned& r0, unsigned& r1, unsigned& r2, unsigned& r3, unsigned a) {
    asm volatile("ldmatrix.sync.aligned.m8n8.x4.shared.b16 {%0,%1,%2,%3}, [%4];"
                 : "=r"(r0), "=r"(r1), "=r"(r2), "=r"(r3) : "r"(a));
}
__device__ __forceinline__ void ldsm4t(unsigned& r0, unsigned& r1, unsigned& r2, unsigned& r3, unsigned a) {
    asm volatile("ldmatrix.sync.aligned.m8n8.x4.trans.shared.b16 {%0,%1,%2,%3}, [%4];"
                 : "=r"(r0), "=r"(r1), "=r"(r2), "=r"(r3) : "r"(a));
}
__device__ __forceinline__ void mma16(float* c, const unsigned* a, unsigned b0, unsigned b1) {
    asm volatile(
        "mma.sync.aligned.m16n8k16.row.col.f32.bf16.bf16.f32 "
        "{%0,%1,%2,%3}, {%4,%5,%6,%7}, {%8,%9}, {%0,%1,%2,%3};"
        : "+f"(c[0]), "+f"(c[1]), "+f"(c[2]), "+f"(c[3])
        : "r"(a[0]), "r"(a[1]), "r"(a[2]), "r"(a[3]), "r"(b0), "r"(b1));
}

// ---------------------------------------------------------------------------
// fp32 SIMT GEMM (proj_in: feeds the residual identity path)
// ---------------------------------------------------------------------------
__global__ __launch_bounds__(256) void gemm128(
    const float* __restrict__ A, const float* __restrict__ Bmat,
    float* __restrict__ C, int M, int N, int K)
{
    const int n0 = blockIdx.x * 128;
    const int m0 = blockIdx.y * 128;
    const int bz = blockIdx.z;
    Bmat += (size_t)bz * K * N;
    C    += (size_t)bz * M * N;

    __shared__ float As[8][132];
    __shared__ float Bs[8][128];

    const int t  = threadIdx.x;
    const int tx = t & 15;
    const int ty = t >> 4;
    const int am = t >> 1;
    const int ak = (t & 1) * 4;
    const int bk = t >> 5;
    const int bn = (t & 31) * 4;

    float acc[8][8];
#pragma unroll
    for (int i = 0; i < 8; i++)
#pragma unroll
        for (int j = 0; j < 8; j++) acc[i][j] = 0.f;

    for (int kt = 0; kt < K; kt += 8) {
        float4 av = *(const float4*)&A[(size_t)(m0 + am) * K + kt + ak];
        float4 bv = *(const float4*)&Bmat[(size_t)(kt + bk) * N + n0 + bn];
        __syncthreads();
        As[ak + 0][am] = av.x;
        As[ak + 1][am] = av.y;
        As[ak + 2][am] = av.z;
        As[ak + 3][am] = av.w;
        *(float4*)&Bs[bk][bn] = bv;
        __syncthreads();
#pragma unroll
        for (int kk = 0; kk < 8; kk++) {
            float a[8], b[8];
#pragma unroll
            for (int i = 0; i < 8; i++) a[i] = As[kk][ty + 16 * i];
#pragma unroll
            for (int j = 0; j < 8; j++) b[j] = Bs[kk][tx + 16 * j];
#pragma unroll
            for (int i = 0; i < 8; i++)
#pragma unroll
                for (int j = 0; j < 8; j++) acc[i][j] += a[i] * b[j];
        }
    }
#pragma unroll
    for (int i = 0; i < 8; i++)
#pragma unroll
        for (int j = 0; j < 8; j++)
            C[(size_t)(m0 + ty + 16 * i) * N + n0 + tx + 16 * j] = acc[i][j];
}

// ---------------------------------------------------------------------------
// bf16 tensor-core GEMM. MODE 0: plain f32 out. MODE 1: +Res. MODE 2: prescale
// epilogue — C is g_pre base (bf16), Res is g_prob; writes 3 cluster-scaled
// bf16 copies (q part additionally scaled by SCALE*LOG2E).
// ---------------------------------------------------------------------------
template <int MODE>
__global__ __launch_bounds__(256, 2) void gemm_bf16(
    const float* __restrict__ A, const float* __restrict__ Bmat,
    float* __restrict__ C, const float* __restrict__ Res,
    int M, int N, int K)
{
    const int n0 = blockIdx.x * 128;
    const int m0 = blockIdx.y * 128;
    const int bz = blockIdx.z;
    Bmat += (size_t)bz * K * N;

    __shared__ __align__(16) __nv_bfloat16 As[128][40];
    __shared__ __align__(16) __nv_bfloat16 Bs[32][136];

    const int t    = threadIdx.x;
    const int lane = t & 31;
    const int w    = t >> 5;
    const int g    = lane >> 2;
    const int tg   = lane & 3;
    const int wm   = (w >> 2) * 64;
    const int wn   = (w & 3) * 32;

    float acc[4][4][4];
#pragma unroll
    for (int mb = 0; mb < 4; mb++)
#pragma unroll
        for (int nb = 0; nb < 4; nb++)
#pragma unroll
            for (int e = 0; e < 4; e++) acc[mb][nb][e] = 0.f;

    const int lam = t >> 3, lak = (t & 7) * 4;
    const int lbk = t >> 5, lbn = (t & 31) * 4;

    for (int kt = 0; kt < K; kt += 32) {
        __syncthreads();
#pragma unroll
        for (int p = 0; p < 4; p++) {
            float4 v = *(const float4*)&A[(size_t)(m0 + lam + 32 * p) * K + kt + lak];
            *(unsigned*)&As[lam + 32 * p][lak]     = pack_bf2(v.x, v.y);
            *(unsigned*)&As[lam + 32 * p][lak + 2] = pack_bf2(v.z, v.w);
        }
#pragma unroll
        for (int p = 0; p < 4; p++) {
            float4 v = *(const float4*)&Bmat[(size_t)(kt + lbk + 8 * p) * N + n0 + lbn];
            *(unsigned*)&Bs[lbk + 8 * p][lbn]     = pack_bf2(v.x, v.y);
            *(unsigned*)&Bs[lbk + 8 * p][lbn + 2] = pack_bf2(v.z, v.w);
        }
        __syncthreads();
#pragma unroll
        for (int ks = 0; ks < 2; ks++) {
            unsigned a[4][4], bb[2][4];
#pragma unroll
            for (int mb = 0; mb < 4; mb++) {
                int row = wm + 16 * mb + (lane & 7) + ((lane & 8) ? 8 : 0);
                int col = 16 * ks + ((lane >= 16) ? 8 : 0);
                ldsm4(a[mb][0], a[mb][1], a[mb][2], a[mb][3], saddr(&As[row][col]));
            }
#pragma unroll
            for (int np = 0; np < 2; np++) {
                int row = 16 * ks + (lane & 7) + ((lane & 8) ? 8 : 0);
                int col = wn + 16 * np + ((lane >= 16) ? 8 : 0);
                ldsm4t(bb[np][0], bb[np][1], bb[np][2], bb[np][3], saddr(&Bs[row][col]));
            }
#pragma unroll
            for (int mb = 0; mb < 4; mb++)
#pragma unroll
                for (int nb = 0; nb < 4; nb++)
                    mma16(acc[mb][nb], a[mb], bb[nb >> 1][(nb & 1) * 2], bb[nb >> 1][(nb & 1) * 2 + 1]);
        }
    }

    if (MODE == 2) {
        // prescale epilogue: part 0=q,1=k,2=v ; crow = channel within part
        const int part = m0 >> 8;
        const float sc = (part == 0) ? QSC : 1.f;
        __nv_bfloat16* pre = (__nv_bfloat16*)C;
        const float* prob = Res + (size_t)bz * KC * NN;
#pragma unroll
        for (int nb = 0; nb < 4; nb++) {
            const int n = n0 + wn + 8 * nb + 2 * tg;
            float2 pr[KC];
#pragma unroll
            for (int i = 0; i < KC; i++) pr[i] = *(const float2*)&prob[i * NN + n];
#pragma unroll
            for (int mb = 0; mb < 4; mb++) {
                const int crow = (m0 & 255) + wm + 16 * mb + g;
#pragma unroll
                for (int i = 0; i < KC; i++) {
                    __nv_bfloat16* base = pre + (((size_t)(part * KC + i) * BB + bz) * C2) * NN;
                    unsigned lo = pack_bf2(acc[mb][nb][0] * pr[i].x * sc, acc[mb][nb][1] * pr[i].y * sc);
                    unsigned hi = pack_bf2(acc[mb][nb][2] * pr[i].x * sc, acc[mb][nb][3] * pr[i].y * sc);
                    *(unsigned*)&base[(size_t)crow * NN + n]       = lo;
                    *(unsigned*)&base[(size_t)(crow + 8) * NN + n] = hi;
                }
            }
        }
        return;
    }

    float* Cb = C + (size_t)bz * M * N;
    const float* R = (MODE == 1) ? (Res + (size_t)bz * M * N) : nullptr;
#pragma unroll
    for (int mb = 0; mb < 4; mb++) {
        const int mr = m0 + wm + 16 * mb;
#pragma unroll
        for (int nb = 0; nb < 4; nb++) {
            const int nc = n0 + wn + 8 * nb + 2 * tg;
            const size_t i0 = (size_t)(mr + g) * N + nc;
            const size_t i1 = (size_t)(mr + g + 8) * N + nc;
            float2 v0 = make_float2(acc[mb][nb][0], acc[mb][nb][1]);
            float2 v1 = make_float2(acc[mb][nb][2], acc[mb][nb][3]);
            if (MODE == 1) {
                float2 r0 = *(const float2*)&R[i0];
                float2 r1 = *(const float2*)&R[i1];
                v0.x += r0.x; v0.y += r0.y; v1.x += r1.x; v1.y += r1.y;
            }
            *(float2*)&Cb[i0] = v0;
            *(float2*)&Cb[i1] = v1;
        }
    }
}

// ---------------------------------------------------------------------------
// Cluster logits + softmax over KC=3
// ---------------------------------------------------------------------------
__global__ __launch_bounds__(256) void cluster_kernel(
    const float* __restrict__ Wc, const float* __restrict__ bc)
{
    const int b = blockIdx.y;
    const int n = blockIdx.x * 256 + threadIdx.x;

    __shared__ float Wcs[KC][C2];
    __shared__ float bcs[KC];
    for (int i = threadIdx.x; i < KC * C2; i += 256) Wcs[i / C2][i % C2] = Wc[i];
    if (threadIdx.x < KC) bcs[threadIdx.x] = bc[threadIdx.x];
    __syncthreads();

    const float* xb = g_xf + (size_t)b * C2 * NN;
    float a0 = bcs[0], a1 = bcs[1], a2 = bcs[2];
#pragma unroll 4
    for (int c = 0; c < C2; c++) {
        float xv = xb[(size_t)c * NN + n];
        a0 += Wcs[0][c] * xv;
        a1 += Wcs[1][c] * xv;
        a2 += Wcs[2][c] * xv;
    }
    float mm = fmaxf(a0, fmaxf(a1, a2));
    float e0 = __expf(a0 - mm), e1 = __expf(a1 - mm), e2 = __expf(a2 - mm);
    float inv = 1.f / (e0 + e1 + e2);
    g_prob[(size_t)(b * KC + 0) * NN + n] = e0 * inv;
    g_prob[(size_t)(b * KC + 1) * NN + n] = e1 * inv;
    g_prob[(size_t)(b * KC + 2) * NN + n] = e2 * inv;
}

// ---------------------------------------------------------------------------
// Clustered attention on prescaled operands: for each cluster i,
//   S_i = Q_i @ K_i^T   (exp2 argument directly — no scalar multiplies)
//   p   = ex2(S_i); lacc += p; PV via mma with P raw and V_i (pk folded).
// 128 threads (4 warps), q-tile 64 (warp w: rows 16w..16w+15), k-tile 64.
// ---------------------------------------------------------------------------
#define QP 72  // bf16 pitch
__global__ __launch_bounds__(128, 3) void attn_kernel()
{
    const int q0 = blockIdx.x * 64;
    const int h  = blockIdx.y;
    const int b  = blockIdx.z;
    const int t    = threadIdx.x;
    const int lane = t & 31;
    const int w    = t >> 5;
    const int g    = lane >> 2;
    const int tg   = lane & 3;

    __shared__ __align__(16) __nv_bfloat16 Qs[KC][32][QP];
    __shared__ __align__(16) __nv_bfloat16 Ks[KC][32][QP];
    __shared__ __align__(16) __nv_bfloat16 Vs[KC][32][QP];

    const int lrow = t >> 2;         // 0..31  (d row)
    const int lch  = (t & 3) * 16;   // 0,16,32,48 (token col chunk)

    // bases for (part, cluster): g_pre[part][i][b][h*32 + d][n]
    const __nv_bfloat16* qb[KC];
    const __nv_bfloat16* kb[KC];
    const __nv_bfloat16* vb[KC];
#pragma unroll
    for (int i = 0; i < KC; i++) {
        qb[i] = g_pre + (((size_t)(0 * KC + i) * BB + b) * C2 + h * DD) * NN;
        kb[i] = g_pre + (((size_t)(1 * KC + i) * BB + b) * C2 + h * DD) * NN;
        vb[i] = g_pre + (((size_t)(2 * KC + i) * BB + b) * C2 + h * DD) * NN;
    }

    // Load Q tiles (once)
#pragma unroll
    for (int i = 0; i < KC; i++) {
        const uint4* s = (const uint4*)(qb[i] + (size_t)lrow * NN + q0 + lch);
        uint4 a = s[0], b2 = s[1];
        __nv_bfloat16* d = &Qs[i][lrow][lch];
        ((uint2*)d)[0] = make_uint2(a.x, a.y);
        ((uint2*)d)[1] = make_uint2(a.z, a.w);
        ((uint2*)d)[2] = make_uint2(b2.x, b2.y);
        ((uint2*)d)[3] = make_uint2(b2.z, b2.w);
    }

    float lacc[KC][2];
    float acc[KC][4][4];
#pragma unroll
    for (int i = 0; i < KC; i++) {
        lacc[i][0] = 0.f; lacc[i][1] = 0.f;
#pragma unroll
        for (int jn = 0; jn < 4; jn++)
#pragma unroll
            for (int e = 0; e < 4; e++) acc[i][jn][e] = 0.f;
    }

    for (int k0 = 0; k0 < NN; k0 += 64) {
        __syncthreads();
#pragma unroll
        for (int i = 0; i < KC; i++) {
            const uint4* sk = (const uint4*)(kb[i] + (size_t)lrow * NN + k0 + lch);
            const uint4* sv = (const uint4*)(vb[i] + (size_t)lrow * NN + k0 + lch);
            uint4 ka = sk[0], kb2 = sk[1];
            uint4 va = sv[0], vb2 = sv[1];
            __nv_bfloat16* dk = &Ks[i][lrow][lch];
            __nv_bfloat16* dv = &Vs[i][lrow][lch];
            ((uint2*)dk)[0] = make_uint2(ka.x, ka.y);
            ((uint2*)dk)[1] = make_uint2(ka.z, ka.w);
            ((uint2*)dk)[2] = make_uint2(kb2.x, kb2.y);
            ((uint2*)dk)[3] = make_uint2(kb2.z, kb2.w);
            ((uint2*)dv)[0] = make_uint2(va.x, va.y);
            ((uint2*)dv)[1] = make_uint2(va.z, va.w);
            ((uint2*)dv)[2] = make_uint2(vb2.x, vb2.y);
            ((uint2*)dv)[3] = make_uint2(vb2.z, vb2.w);
        }
        __syncthreads();

#pragma unroll
        for (int i = 0; i < KC; i++) {
            // Q fragments for this cluster
            unsigned aQ[2][4];
#pragma unroll
            for (int ds = 0; ds < 2; ds++) {
                int row = 16 * ds + (lane & 7) + ((lane >= 16) ? 8 : 0);
                int col = 16 * w + ((lane & 8) ? 8 : 0);
                ldsm4t(aQ[ds][0], aQ[ds][1], aQ[ds][2], aQ[ds][3], saddr(&Qs[i][row][col]));
            }
            // S[16 x 64] = Q_i @ K_i^T  — already the exp2 argument
            float S[8][4];
#pragma unroll
            for (int j = 0; j < 8; j++)
#pragma unroll
                for (int e = 0; e < 4; e++) S[j][e] = 0.f;
#pragma unroll
            for (int ds = 0; ds < 2; ds++) {
#pragma unroll
                for (int jp = 0; jp < 4; jp++) {
                    unsigned b0a, b1a, b0b, b1b;
                    int row = 16 * ds + (lane & 7) + ((lane & 8) ? 8 : 0);
                    int col = 16 * jp + ((lane >= 16) ? 8 : 0);
                    ldsm4t(b0a, b1a, b0b, b1b, saddr(&Ks[i][row][col]));
                    mma16(S[2 * jp],     aQ[ds], b0a, b1a);
                    mma16(S[2 * jp + 1], aQ[ds], b0b, b1b);
                }
            }
            // softmax (no-max, exp2): p = ex2(S)
            unsigned aP[4][4];
#pragma unroll
            for (int j = 0; j < 8; j++) {
                float p00 = ex2(S[j][0]);
                float p01 = ex2(S[j][1]);
                float p10 = ex2(S[j][2]);
                float p11 = ex2(S[j][3]);
                lacc[i][0] += p00 + p01;
                lacc[i][1] += p10 + p11;
                aP[j >> 1][(j & 1) * 2]     = pack_bf2(p00, p01);
                aP[j >> 1][(j & 1) * 2 + 1] = pack_bf2(p10, p11);
            }
            // PV: acc_i += P @ V_i
#pragma unroll
            for (int kk = 0; kk < 4; kk++) {
#pragma unroll
                for (int jp = 0; jp < 2; jp++) {
                    unsigned v0, v1, v2, v3;
                    int row = 8 * (2 * jp + ((lane >= 16) ? 1 : 0)) + (lane & 7);
                    int col = 16 * kk + ((lane & 8) ? 8 : 0);
                    ldsm4(v0, v1, v2, v3, saddr(&Vs[i][row][col]));
                    mma16(acc[i][2 * jp],     aP[kk], v0, v1);
                    mma16(acc[i][2 * jp + 1], aP[kk], v2, v3);
                }
            }
        }
    }

    // Epilogue: reduce l over quad, combine clusters, stage [d][q], write out
    __syncthreads();
    float* Os = (float*)&Qs[0][0][0];  // [32][65] overlay
    float r0[KC], r1[KC];
#pragma unroll
    for (int i = 0; i < KC; i++) {
        float l0 = lacc[i][0];
        l0 += __shfl_xor_sync(0xffffffffu, l0, 1);
        l0 += __shfl_xor_sync(0xffffffffu, l0, 2);
        float l1 = lacc[i][1];
        l1 += __shfl_xor_sync(0xffffffffu, l1, 1);
        l1 += __shfl_xor_sync(0xffffffffu, l1, 2);
        r0[i] = 1.f / (3.f * l0);
        r1[i] = 1.f / (3.f * l1);
    }
    const int qg = 16 * w + g;
#pragma unroll
    for (int jn = 0; jn < 4; jn++) {
        int d0 = 8 * jn + 2 * tg;
        float o00 = acc[0][jn][0] * r0[0] + acc[1][jn][0] * r0[1] + acc[2][jn][0] * r0[2];
        float o01 = acc[0][jn][1] * r0[0] + acc[1][jn][1] * r0[1] + acc[2][jn][1] * r0[2];
        float o10 = acc[0][jn][2] * r1[0] + acc[1][jn][2] * r1[1] + acc[2][jn][2] * r1[2];
        float o11 = acc[0][jn][3] * r1[0] + acc[1][jn][3] * r1[1] + acc[2][jn][3] * r1[2];
        Os[d0 * 65 + qg]           = o00;
        Os[(d0 + 1) * 65 + qg]     = o01;
        Os[d0 * 65 + qg + 8]       = o10;
        Os[(d0 + 1) * 65 + qg + 8] = o11;
    }
    __syncthreads();
    float* ob = g_att + (size_t)(b * C2 + h * DD) * NN;
#pragma unroll
    for (int j = 0; j < 16; j++) {
        int i = t + 128 * j, d = i >> 6, q = i & 63;
        ob[(size_t)d * NN + q0 + q] = Os[d * 65 + q];
    }
}

// ---------------------------------------------------------------------------
extern "C" void kernel_launch(void* const* d_in, const int* in_sizes, int n_in,
                              void* d_out, int out_size)
{
    const float* x         = (const float*)d_in[0];
    const float* W_in      = (const float*)d_in[1];
    const float* W_cluster = (const float*)d_in[2];
    const float* b_cluster = (const float*)d_in[3];
    const float* W_qkv     = (const float*)d_in[4];
    const float* W_proj    = (const float*)d_in[5];
    float* out = (float*)d_out;

    float *xf, *att, *prob;
    __nv_bfloat16* pre;
    cudaGetSymbolAddress((void**)&xf,   g_xf);
    cudaGetSymbolAddress((void**)&att,  g_att);
    cudaGetSymbolAddress((void**)&prob, g_prob);
    cudaGetSymbolAddress((void**)&pre,  g_pre);

    // proj_in (fp32 — residual identity path)
    gemm128<<<dim3(NN / 128, C2 / 128, BB), 256>>>(W_in, x, xf, C2, NN, C1);
    // cluster probs
    cluster_kernel<<<dim3(4, BB), 256>>>(W_cluster, b_cluster);
    // qkv (bf16 tensor) + cluster-prescale epilogue -> g_pre (bf16, 3 clusters)
    gemm_bf16<2><<<dim3(NN / 128, 768 / 128, BB), 256>>>(W_qkv, xf, (float*)pre, prob, 3 * C2, NN, C2);
    // clustered attention on prescaled operands
    attn_kernel<<<dim3(NN / 64, HEADS, BB), 128>>>();
    // proj_out + residual (bf16 tensor, fp32 residual add)
    gemm_bf16<1><<<dim3(NN / 128, C2 / 128, BB), 256>>>(W_proj, att, out, xf, C2, NN, C2);
}